// round 3
// baseline (speedup 1.0000x reference)
#include <cuda_runtime.h>
#include <math.h>

// Problem constants (fixed-shape problem)
#define NN 50000     // nodes
#define EE 800000    // edges
#define GG 128       // graphs
#define HH 128       // hidden dim
#define KK3 3        // GMM kernels
#define LL 4         // layers
#define NC 10        // classes
#define BN_EPS 1e-5f

// ---------------------------------------------------------------------------
// Device scratch (static; no allocation at runtime)
// ---------------------------------------------------------------------------
__device__ float  g_h[NN * HH];              // current node features (25.6 MB)
__device__ float  g_s[NN * KK3 * HH];        // aggregated weighted sums (76.8 MB)
__device__ float  g_agg[NN * HH];            // GEMM output per layer (25.6 MB)
__device__ float4 g_w4[EE];                  // per-edge GMM weights (CSR order)
__device__ float2 g_pseudo[EE];              // per-edge pseudo coords (CSR order)
__device__ int    g_deg_r[NN];
__device__ int    g_deg_c[NN];
__device__ int    g_cursor[NN];
__device__ int    g_off[NN + 1];             // CSR offsets by col
__device__ int    g_csr_row[EE];             // source node per CSR slot
__device__ float  g_Bt[LL * KK3 * HH * HH];  // transposed fc weights
__device__ float  g_embT[HH * HH];           // transposed embedding weights
__device__ float  g_bn[2 * HH];              // column sum / sumsq
__device__ float  g_hg[GG * HH];             // per-graph readout

// ---------------------------------------------------------------------------
// CSR build
// ---------------------------------------------------------------------------
__global__ void zero_int3_kernel() {
    int i = blockIdx.x * blockDim.x + threadIdx.x;
    if (i < NN) { g_deg_r[i] = 0; g_deg_c[i] = 0; g_cursor[i] = 0; }
}

__global__ void degrees_kernel(const int* __restrict__ ei) {
    int e = blockIdx.x * blockDim.x + threadIdx.x;
    if (e < EE) {
        atomicAdd(&g_deg_r[ei[e]], 1);
        atomicAdd(&g_deg_c[ei[EE + e]], 1);
    }
}

// One-block exclusive scan of g_deg_c -> g_off (warp-shuffle based)
__global__ void scan_kernel() {
    __shared__ int warp_sums[32];
    int tid = threadIdx.x, lane = tid & 31, wid = tid >> 5;
    int running = 0;
    for (int base = 0; base < NN; base += 1024) {
        int i = base + tid;
        int v = (i < NN) ? g_deg_c[i] : 0;
        int x = v;
        #pragma unroll
        for (int off = 1; off < 32; off <<= 1) {
            int t = __shfl_up_sync(0xffffffffu, x, off);
            if (lane >= off) x += t;
        }
        if (lane == 31) warp_sums[wid] = x;
        __syncthreads();
        if (wid == 0) {
            int y = warp_sums[lane];
            #pragma unroll
            for (int off = 1; off < 32; off <<= 1) {
                int t = __shfl_up_sync(0xffffffffu, y, off);
                if (lane >= off) y += t;
            }
            warp_sums[lane] = y;
        }
        __syncthreads();
        int woff = (wid > 0) ? warp_sums[wid - 1] : 0;
        if (i < NN) g_off[i] = running + woff + x - v;
        running += warp_sums[31];
        __syncthreads();
    }
    if (tid == 0) g_off[NN] = running;
}

__global__ void fill_csr_kernel(const int* __restrict__ ei) {
    int e = blockIdx.x * blockDim.x + threadIdx.x;
    if (e < EE) {
        int r = ei[e], c = ei[EE + e];
        int p = g_off[c] + atomicAdd(&g_cursor[c], 1);
        g_csr_row[p] = r;
        float sr = rsqrtf((float)g_deg_r[r] + 1.0f);
        float sd = rsqrtf((float)g_deg_c[c] + 1.0f);
        g_pseudo[p] = make_float2(sr, sd);
    }
}

// ---------------------------------------------------------------------------
// Weight prep: transpose emb_w and fc_w for coalesced GEMM B reads
//   g_embT[i*H + j]            = emb_w[j*H + i]
//   g_Bt[l][(k*H+i)*H + j]     = fc_w[l][(k*H+j)*H + i]
// ---------------------------------------------------------------------------
__global__ void prep_weights_kernel(const float* __restrict__ emb_w,
                                    const float* __restrict__ fc_w) {
    const int TOT = HH * HH + LL * KK3 * HH * HH;
    for (int idx = blockIdx.x * blockDim.x + threadIdx.x; idx < TOT;
         idx += gridDim.x * blockDim.x) {
        if (idx < HH * HH) {
            int i = idx / HH, j = idx % HH;
            g_embT[i * HH + j] = emb_w[j * HH + i];
        } else {
            int t = idx - HH * HH;
            int l = t / (KK3 * HH * HH);
            int rem = t % (KK3 * HH * HH);
            int kc = rem / HH;            // k*H + i
            int j = rem % HH;
            int k = kc / HH, i = kc % HH;
            g_Bt[t] = fc_w[((l * KK3 + k) * HH + j) * HH + i];
        }
    }
}

// ---------------------------------------------------------------------------
// SGEMM: C[NN,128] = A[NN,Kd] @ B[Kd,128] (+ bias)
// 128x128 tile, BK=16, 256 threads, 8x8 micro-tile
// ---------------------------------------------------------------------------
__device__ __forceinline__ void gemm_core(const float* __restrict__ A,
                                          const float* __restrict__ B,
                                          const float* __restrict__ bias,
                                          float* __restrict__ C, int Kd) {
    __shared__ float As[16][128];
    __shared__ float Bs[16][128];
    const int tid = threadIdx.x;
    const int tx = tid & 15, ty = tid >> 4;
    const int rowBase = blockIdx.x * 128;
    float acc[8][8];
    #pragma unroll
    for (int i = 0; i < 8; i++)
        #pragma unroll
        for (int j = 0; j < 8; j++) acc[i][j] = 0.0f;

    for (int k0 = 0; k0 < Kd; k0 += 16) {
        // load A tile (128 x 16), store transposed
        #pragma unroll
        for (int jj = 0; jj < 2; jj++) {
            int f = tid * 2 + jj;
            int r = f >> 2;
            int kk4 = (f & 3) * 4;
            float4 v = make_float4(0.f, 0.f, 0.f, 0.f);
            int grow = rowBase + r;
            if (grow < NN)
                v = *(const float4*)&A[(size_t)grow * Kd + k0 + kk4];
            As[kk4 + 0][r] = v.x; As[kk4 + 1][r] = v.y;
            As[kk4 + 2][r] = v.z; As[kk4 + 3][r] = v.w;
        }
        // load B tile (16 x 128)
        #pragma unroll
        for (int jj = 0; jj < 2; jj++) {
            int f = tid * 2 + jj;
            int kk = f >> 5;
            int c = (f & 31) * 4;
            *(float4*)&Bs[kk][c] = *(const float4*)&B[(size_t)(k0 + kk) * 128 + c];
        }
        __syncthreads();
        #pragma unroll
        for (int kk = 0; kk < 16; kk++) {
            float a[8], b[8];
            #pragma unroll
            for (int i = 0; i < 8; i++) a[i] = As[kk][ty * 8 + i];
            #pragma unroll
            for (int j = 0; j < 8; j++) b[j] = Bs[kk][tx * 8 + j];
            #pragma unroll
            for (int i = 0; i < 8; i++)
                #pragma unroll
                for (int j = 0; j < 8; j++)
                    acc[i][j] = fmaf(a[i], b[j], acc[i][j]);
        }
        __syncthreads();
    }
    #pragma unroll
    for (int i = 0; i < 8; i++) {
        int grow = rowBase + ty * 8 + i;
        if (grow >= NN) continue;
        #pragma unroll
        for (int j = 0; j < 8; j += 4) {
            int c = tx * 8 + j;
            float4 v = make_float4(acc[i][j], acc[i][j + 1], acc[i][j + 2], acc[i][j + 3]);
            if (bias) {
                v.x += bias[c]; v.y += bias[c + 1];
                v.z += bias[c + 2]; v.w += bias[c + 3];
            }
            *(float4*)&C[(size_t)grow * 128 + c] = v;
        }
    }
}

__global__ void gemm_emb_kernel(const float* __restrict__ feature,
                                const float* __restrict__ emb_b) {
    gemm_core(feature, g_embT, emb_b, g_h, HH);
}

__global__ void gemm_layer_kernel(int l) {
    gemm_core(g_s, &g_Bt[(size_t)l * KK3 * HH * HH], nullptr, g_agg, KK3 * HH);
}

// ---------------------------------------------------------------------------
// Per-layer edge weights (CSR-ordered)
// ---------------------------------------------------------------------------
__global__ void edge_weight_kernel(int l, const float* __restrict__ pp_w,
                                   const float* __restrict__ pp_b,
                                   const float* __restrict__ mu,
                                   const float* __restrict__ inv_sigma) {
    int e = blockIdx.x * blockDim.x + threadIdx.x;
    if (e >= EE) return;
    float2 p = g_pseudo[e];
    float ps[2];
    #pragma unroll
    for (int d = 0; d < 2; d++) {
        float a = pp_w[(l * 2 + d) * 2 + 0] * p.x + pp_w[(l * 2 + d) * 2 + 1] * p.y
                + pp_b[l * 2 + d];
        ps[d] = tanhf(a);
    }
    float wk[3];
    #pragma unroll
    for (int k = 0; k < 3; k++) {
        float acc = 0.f;
        #pragma unroll
        for (int d = 0; d < 2; d++) {
            float diff = ps[d] - mu[(l * 3 + k) * 2 + d];
            float is = inv_sigma[(l * 3 + k) * 2 + d];
            acc += diff * diff * is * is;
        }
        wk[k] = expf(-0.5f * acc);
    }
    g_w4[e] = make_float4(wk[0], wk[1], wk[2], 0.f);
}

// ---------------------------------------------------------------------------
// Aggregation: one warp per destination node
//   g_s[c][k*H + i] = sum_{e -> c} w[e,k] * g_h[row_e][i]
// Also zeroes the BN accumulators (runs before bn_stats each layer).
// ---------------------------------------------------------------------------
__global__ void aggregate_kernel() {
    if (blockIdx.x == 0 && threadIdx.x < 256) g_bn[threadIdx.x] = 0.f;
    int gw = blockIdx.x * 8 + (threadIdx.x >> 5);
    int lane = threadIdx.x & 31;
    if (gw >= NN) return;
    int start = g_off[gw], end = g_off[gw + 1];
    float4 a0 = make_float4(0.f, 0.f, 0.f, 0.f);
    float4 a1 = a0, a2 = a0;

    int e = start;
    int r_next = 0;
    float4 w_next = a0;
    if (e < end) { r_next = g_csr_row[e]; w_next = g_w4[e]; }
    for (; e < end; e++) {
        int r = r_next;
        float4 wv = w_next;
        if (e + 1 < end) { r_next = g_csr_row[e + 1]; w_next = g_w4[e + 1]; }
        float4 hv = *(const float4*)&g_h[(size_t)r * HH + lane * 4];
        a0.x = fmaf(wv.x, hv.x, a0.x); a0.y = fmaf(wv.x, hv.y, a0.y);
        a0.z = fmaf(wv.x, hv.z, a0.z); a0.w = fmaf(wv.x, hv.w, a0.w);
        a1.x = fmaf(wv.y, hv.x, a1.x); a1.y = fmaf(wv.y, hv.y, a1.y);
        a1.z = fmaf(wv.y, hv.z, a1.z); a1.w = fmaf(wv.y, hv.w, a1.w);
        a2.x = fmaf(wv.z, hv.x, a2.x); a2.y = fmaf(wv.z, hv.y, a2.y);
        a2.z = fmaf(wv.z, hv.z, a2.z); a2.w = fmaf(wv.z, hv.w, a2.w);
    }
    size_t base = (size_t)gw * (KK3 * HH) + lane * 4;
    *(float4*)&g_s[base] = a0;
    *(float4*)&g_s[base + HH] = a1;
    *(float4*)&g_s[base + 2 * HH] = a2;
}

// ---------------------------------------------------------------------------
// BN statistics + apply (ReLU + residual into g_h)
// ---------------------------------------------------------------------------
__global__ void bn_stats_kernel() {
    __shared__ float ssum[256], ssq[256];
    int tid = threadIdx.x;
    int ch = tid & 127, half = tid >> 7;
    float s = 0.f, q = 0.f;
    for (int r = blockIdx.x * 2 + half; r < NN; r += gridDim.x * 2) {
        float v = g_agg[(size_t)r * HH + ch];
        s += v; q += v * v;
    }
    ssum[tid] = s; ssq[tid] = q;
    __syncthreads();
    if (tid < 128) {
        s = ssum[tid] + ssum[tid + 128];
        q = ssq[tid] + ssq[tid + 128];
        atomicAdd(&g_bn[ch], s);
        atomicAdd(&g_bn[128 + ch], q);
    }
}

__global__ void bn_apply_kernel(int l, const float* __restrict__ gamma,
                                const float* __restrict__ beta) {
    int idx = blockIdx.x * blockDim.x + threadIdx.x;     // over N*H/4
    if (idx >= NN * HH / 4) return;
    int ch = (idx * 4) & 127;
    const float inv_n = 1.0f / (float)NN;
    float4 a = *(const float4*)&g_agg[(size_t)idx * 4];
    float4 h = *(const float4*)&g_h[(size_t)idx * 4];
    #pragma unroll
    for (int c = 0; c < 4; c++) {
        float mean = g_bn[ch + c] * inv_n;
        float var = g_bn[128 + ch + c] * inv_n - mean * mean;
        float inv = rsqrtf(var + BN_EPS);
        float av = (c == 0) ? a.x : (c == 1) ? a.y : (c == 2) ? a.z : a.w;
        float hv = (c == 0) ? h.x : (c == 1) ? h.y : (c == 2) ? h.z : h.w;
        float bn = (av - mean) * inv * gamma[l * HH + ch + c] + beta[l * HH + ch + c];
        float nv = hv + fmaxf(bn, 0.f);
        if (c == 0) h.x = nv; else if (c == 1) h.y = nv;
        else if (c == 2) h.z = nv; else h.w = nv;
    }
    *(float4*)&g_h[(size_t)idx * 4] = h;
}

// ---------------------------------------------------------------------------
// Readout (mean per graph) + MLP head
// ---------------------------------------------------------------------------
__global__ void readout_kernel(const int* __restrict__ batch) {
    int g = blockIdx.x, tid = threadIdx.x;   // 128 threads
    int lo = 0, hi = NN;
    while (lo < hi) { int m = (lo + hi) >> 1; if (batch[m] < g) lo = m + 1; else hi = m; }
    int start = lo;
    lo = start; hi = NN;
    while (lo < hi) { int m = (lo + hi) >> 1; if (batch[m] <= g) lo = m + 1; else hi = m; }
    int end = lo;
    float acc = 0.f;
    for (int n = start; n < end; n++) acc += g_h[(size_t)n * HH + tid];
    float cnt = (float)(end - start);
    g_hg[g * HH + tid] = acc / fmaxf(cnt, 1.0f);
}

__global__ void mlp_kernel(const float* __restrict__ w0, const float* __restrict__ b0,
                           const float* __restrict__ w1, const float* __restrict__ b1,
                           const float* __restrict__ w2, const float* __restrict__ b2,
                           float* __restrict__ out) {
    __shared__ float sh[128], z0[64], z1[32];
    int g = blockIdx.x, tid = threadIdx.x;
    sh[tid] = g_hg[g * 128 + tid];
    __syncthreads();
    if (tid < 64) {
        float a = b0[tid];
        #pragma unroll 8
        for (int i = 0; i < 128; i++) a = fmaf(w0[tid * 128 + i], sh[i], a);
        z0[tid] = fmaxf(a, 0.f);
    }
    __syncthreads();
    if (tid < 32) {
        float a = b1[tid];
        #pragma unroll 8
        for (int i = 0; i < 64; i++) a = fmaf(w1[tid * 64 + i], z0[i], a);
        z1[tid] = fmaxf(a, 0.f);
    }
    __syncthreads();
    if (tid < 10) {
        float a = b2[tid];
        #pragma unroll
        for (int i = 0; i < 32; i++) a = fmaf(w2[tid * 32 + i], z1[i], a);
        out[g * NC + tid] = a;
    }
}

// ---------------------------------------------------------------------------
// Launch
// ---------------------------------------------------------------------------
extern "C" void kernel_launch(void* const* d_in, const int* in_sizes, int n_in,
                              void* d_out, int out_size) {
    const float* feature   = (const float*)d_in[0];
    const int*   edge_index= (const int*)  d_in[1];
    const int*   batch     = (const int*)  d_in[2];
    // d_in[3] = emb_w (used via prep_weights)
    const float* emb_w     = (const float*)d_in[3];
    const float* emb_b     = (const float*)d_in[4];
    const float* fc_w      = (const float*)d_in[5];
    const float* mu        = (const float*)d_in[6];
    const float* inv_sigma = (const float*)d_in[7];
    const float* bn_gamma  = (const float*)d_in[8];
    const float* bn_beta   = (const float*)d_in[9];
    const float* pp_w      = (const float*)d_in[10];
    const float* pp_b      = (const float*)d_in[11];
    const float* mlp_w0    = (const float*)d_in[12];
    const float* mlp_b0    = (const float*)d_in[13];
    const float* mlp_w1    = (const float*)d_in[14];
    const float* mlp_b1    = (const float*)d_in[15];
    const float* mlp_w2    = (const float*)d_in[16];
    const float* mlp_b2    = (const float*)d_in[17];
    float* out = (float*)d_out;

    const int EB = (EE + 255) / 256;        // 3125
    const int GEMM_BLKS = (NN + 127) / 128; // 391

    // -------- precompute (per launch) --------
    zero_int3_kernel<<<(NN + 255) / 256, 256>>>();
    degrees_kernel<<<EB, 256>>>(edge_index);
    scan_kernel<<<1, 1024>>>();
    fill_csr_kernel<<<EB, 256>>>(edge_index);
    prep_weights_kernel<<<1024, 256>>>(emb_w, fc_w);

    // embedding: h = feature @ emb_w.T + emb_b
    gemm_emb_kernel<<<GEMM_BLKS, 256>>>(feature, emb_b);

    // -------- layers --------
    for (int l = 0; l < LL; l++) {
        edge_weight_kernel<<<EB, 256>>>(l, pp_w, pp_b, mu, inv_sigma);
        aggregate_kernel<<<(NN + 7) / 8, 256>>>();
        gemm_layer_kernel<<<GEMM_BLKS, 256>>>(l);
        bn_stats_kernel<<<256, 256>>>();
        bn_apply_kernel<<<(NN * HH / 4 + 255) / 256, 256>>>(l, bn_gamma, bn_beta);
    }

    // -------- readout + MLP --------
    readout_kernel<<<GG, 128>>>(batch);
    mlp_kernel<<<GG, 128>>>(mlp_w0, mlp_b0, mlp_w1, mlp_b1, mlp_w2, mlp_b2, out);
}

// round 6
// speedup vs baseline: 1.1089x; 1.1089x over previous
#include <cuda_runtime.h>
#include <math.h>

// Problem constants (fixed-shape problem)
#define NN 50000     // nodes
#define EE 800000    // edges
#define GG 128       // graphs
#define HH 128       // hidden dim
#define KK3 3        // GMM kernels
#define LL 4         // layers
#define NC 10        // classes
#define BN_EPS 1e-5f

typedef unsigned long long u64;

// ---------------------------------------------------------------------------
// Packed fp32x2 helpers (sm_100+ PTX; ptxas never auto-fuses these)
// ---------------------------------------------------------------------------
__device__ __forceinline__ u64 pack2(float lo, float hi) {
    u64 r; asm("mov.b64 %0, {%1,%2};" : "=l"(r) : "f"(lo), "f"(hi)); return r;
}
__device__ __forceinline__ void unpack2(u64 v, float& lo, float& hi) {
    asm("mov.b64 {%0,%1}, %2;" : "=f"(lo), "=f"(hi) : "l"(v));
}
__device__ __forceinline__ void ffma2(u64& d, u64 a, u64 b) {
    asm("fma.rn.f32x2 %0, %1, %2, %0;" : "+l"(d) : "l"(a), "l"(b));
}

// ---------------------------------------------------------------------------
// Device scratch (static; no allocation at runtime)
// ---------------------------------------------------------------------------
__device__ float  g_h[NN * HH];               // current node features
__device__ float  g_s[NN * KK3 * HH];         // aggregated weighted sums
__device__ float  g_agg[NN * HH];             // GEMM output per layer
__device__ float4 g_w4[LL * EE];              // per-edge GMM weights, all layers (CSR order)
__device__ float2 g_pseudo[EE];               // per-edge pseudo coords (CSR order)
__device__ int    g_deg_r[NN];
__device__ int    g_deg_c[NN];
__device__ int    g_cursor[NN];
__device__ int    g_off[NN + 1];              // CSR offsets by col
__device__ int    g_csr_row[EE];              // source node per CSR slot
__device__ float  g_Bt[LL * KK3 * HH * HH];   // transposed fc weights
__device__ float  g_embT[HH * HH];            // transposed embedding weights
__device__ float  g_bn[2 * HH];               // column sum / sumsq
__device__ float  g_hg[GG * HH];              // per-graph readout

// ---------------------------------------------------------------------------
// CSR build
// ---------------------------------------------------------------------------
__global__ void zero_int3_kernel() {
    int i = blockIdx.x * blockDim.x + threadIdx.x;
    if (i < NN) { g_deg_r[i] = 0; g_deg_c[i] = 0; g_cursor[i] = 0; }
}

__global__ void degrees_kernel(const int* __restrict__ ei) {
    int e = blockIdx.x * blockDim.x + threadIdx.x;
    if (e < EE) {
        atomicAdd(&g_deg_r[ei[e]], 1);
        atomicAdd(&g_deg_c[ei[EE + e]], 1);
    }
}

// One-block exclusive scan of g_deg_c -> g_off (warp-shuffle based)
__global__ void scan_kernel() {
    __shared__ int warp_sums[32];
    int tid = threadIdx.x, lane = tid & 31, wid = tid >> 5;
    int running = 0;
    for (int base = 0; base < NN; base += 1024) {
        int i = base + tid;
        int v = (i < NN) ? g_deg_c[i] : 0;
        int x = v;
        #pragma unroll
        for (int off = 1; off < 32; off <<= 1) {
            int t = __shfl_up_sync(0xffffffffu, x, off);
            if (lane >= off) x += t;
        }
        if (lane == 31) warp_sums[wid] = x;
        __syncthreads();
        if (wid == 0) {
            int y = warp_sums[lane];
            #pragma unroll
            for (int off = 1; off < 32; off <<= 1) {
                int t = __shfl_up_sync(0xffffffffu, y, off);
                if (lane >= off) y += t;
            }
            warp_sums[lane] = y;
        }
        __syncthreads();
        int woff = (wid > 0) ? warp_sums[wid - 1] : 0;
        if (i < NN) g_off[i] = running + woff + x - v;
        running += warp_sums[31];
        __syncthreads();
    }
    if (tid == 0) g_off[NN] = running;
}

__global__ void fill_csr_kernel(const int* __restrict__ ei) {
    int e = blockIdx.x * blockDim.x + threadIdx.x;
    if (e < EE) {
        int r = ei[e], c = ei[EE + e];
        int p = g_off[c] + atomicAdd(&g_cursor[c], 1);
        g_csr_row[p] = r;
        float sr = rsqrtf((float)g_deg_r[r] + 1.0f);
        float sd = rsqrtf((float)g_deg_c[c] + 1.0f);
        g_pseudo[p] = make_float2(sr, sd);
    }
}

// ---------------------------------------------------------------------------
// Weight prep: transpose emb_w and fc_w for coalesced GEMM B reads
// ---------------------------------------------------------------------------
__global__ void prep_weights_kernel(const float* __restrict__ emb_w,
                                    const float* __restrict__ fc_w) {
    const int TOT = HH * HH + LL * KK3 * HH * HH;
    for (int idx = blockIdx.x * blockDim.x + threadIdx.x; idx < TOT;
         idx += gridDim.x * blockDim.x) {
        if (idx < HH * HH) {
            int i = idx / HH, j = idx % HH;
            g_embT[i * HH + j] = emb_w[j * HH + i];
        } else {
            int t = idx - HH * HH;
            int l = t / (KK3 * HH * HH);
            int rem = t % (KK3 * HH * HH);
            int kc = rem / HH;            // k*H + i
            int j = rem % HH;
            int k = kc / HH, i = kc % HH;
            g_Bt[t] = fc_w[((l * KK3 + k) * HH + j) * HH + i];
        }
    }
}

// ---------------------------------------------------------------------------
// SGEMM: C[NN,128] = A[NN,Kd] @ B[Kd,128] (+ bias), packed f32x2 inner loop.
// 128x128 tile, BK=16, 256 threads, 8x8 micro-tile (as 8x4 f32x2 pairs).
// A tile stored value-duplicated so the broadcast operand needs no packing.
// Next-tile global loads are prefetched into registers before the barrier.
// Optionally fuses BN column sum/sumsq accumulation (into g_bn via atomics).
// ---------------------------------------------------------------------------
template <bool DO_BN>
__device__ __forceinline__ void gemm_core(const float* __restrict__ A,
                                          const float* __restrict__ B,
                                          const float* __restrict__ bias,
                                          float* __restrict__ C, int Kd) {
    __shared__ u64   As2[16][128];   // duplicated (v,v) pairs, 16 KB
    __shared__ float Bs[16][128];    // 8 KB
    const int tid = threadIdx.x;
    const int tx = tid & 15, ty = tid >> 4;
    const int rowBase = blockIdx.x * 128;

    // per-thread load coordinates (2 A fragments + 2 B fragments per k-tile)
    const int fA0 = tid * 2,       fA1 = tid * 2 + 1;
    const int rA0 = fA0 >> 2,      rA1 = fA1 >> 2;
    const int kA0 = (fA0 & 3) * 4, kA1 = (fA1 & 3) * 4;
    const int gA0 = rowBase + rA0, gA1 = rowBase + rA1;
    const int kB0 = fA0 >> 5,      kB1 = fA1 >> 5;
    const int cB0 = (fA0 & 31) * 4, cB1 = (fA1 & 31) * 4;

    u64 acc[8][4];
    #pragma unroll
    for (int i = 0; i < 8; i++)
        #pragma unroll
        for (int j = 0; j < 4; j++) acc[i][j] = 0ull;

    // prefetch first tile
    float4 va0 = make_float4(0.f, 0.f, 0.f, 0.f), va1 = va0;
    if (gA0 < NN) va0 = *(const float4*)&A[(size_t)gA0 * Kd + kA0];
    if (gA1 < NN) va1 = *(const float4*)&A[(size_t)gA1 * Kd + kA1];
    float4 vb0 = *(const float4*)&B[(size_t)kB0 * 128 + cB0];
    float4 vb1 = *(const float4*)&B[(size_t)kB1 * 128 + cB1];

    for (int k0 = 0; k0 < Kd; k0 += 16) {
        // store current tile
        As2[kA0 + 0][rA0] = pack2(va0.x, va0.x);
        As2[kA0 + 1][rA0] = pack2(va0.y, va0.y);
        As2[kA0 + 2][rA0] = pack2(va0.z, va0.z);
        As2[kA0 + 3][rA0] = pack2(va0.w, va0.w);
        As2[kA1 + 0][rA1] = pack2(va1.x, va1.x);
        As2[kA1 + 1][rA1] = pack2(va1.y, va1.y);
        As2[kA1 + 2][rA1] = pack2(va1.z, va1.z);
        As2[kA1 + 3][rA1] = pack2(va1.w, va1.w);
        *(float4*)&Bs[kB0][cB0] = vb0;
        *(float4*)&Bs[kB1][cB1] = vb1;
        __syncthreads();

        // prefetch next tile into registers (overlaps with FFMA2 chain below)
        int kn = k0 + 16;
        if (kn < Kd) {
            va0 = make_float4(0.f, 0.f, 0.f, 0.f); va1 = va0;
            if (gA0 < NN) va0 = *(const float4*)&A[(size_t)gA0 * Kd + kn + kA0];
            if (gA1 < NN) va1 = *(const float4*)&A[(size_t)gA1 * Kd + kn + kA1];
            vb0 = *(const float4*)&B[(size_t)(kn + kB0) * 128 + cB0];
            vb1 = *(const float4*)&B[(size_t)(kn + kB1) * 128 + cB1];
        }

        #pragma unroll
        for (int kk = 0; kk < 16; kk++) {
            ulonglong2 av0 = *(const ulonglong2*)&As2[kk][ty * 8 + 0];
            ulonglong2 av1 = *(const ulonglong2*)&As2[kk][ty * 8 + 2];
            ulonglong2 av2 = *(const ulonglong2*)&As2[kk][ty * 8 + 4];
            ulonglong2 av3 = *(const ulonglong2*)&As2[kk][ty * 8 + 6];
            ulonglong2 bv0 = *(const ulonglong2*)&Bs[kk][tx * 8 + 0];
            ulonglong2 bv1 = *(const ulonglong2*)&Bs[kk][tx * 8 + 4];
            u64 a2[8] = {av0.x, av0.y, av1.x, av1.y, av2.x, av2.y, av3.x, av3.y};
            u64 b2[4] = {bv0.x, bv0.y, bv1.x, bv1.y};
            #pragma unroll
            for (int i = 0; i < 8; i++)
                #pragma unroll
                for (int j = 0; j < 4; j++)
                    ffma2(acc[i][j], a2[i], b2[j]);
        }
        __syncthreads();
    }

    // epilogue: unpack, (bias), store
    #pragma unroll
    for (int i = 0; i < 8; i++) {
        int grow = rowBase + ty * 8 + i;
        if (grow >= NN) continue;
        float f[8];
        #pragma unroll
        for (int j = 0; j < 4; j++) unpack2(acc[i][j], f[2 * j], f[2 * j + 1]);
        int c = tx * 8;
        if (bias) {
            #pragma unroll
            for (int j = 0; j < 8; j++) f[j] += bias[c + j];
        }
        *(float4*)&C[(size_t)grow * 128 + c] = make_float4(f[0], f[1], f[2], f[3]);
        *(float4*)&C[(size_t)grow * 128 + c + 4] = make_float4(f[4], f[5], f[6], f[7]);
    }

    if (DO_BN) {
        // per-thread column partials over its 8 rows (tail rows are exact zeros)
        float cs[8], cq[8];
        #pragma unroll
        for (int j = 0; j < 8; j++) { cs[j] = 0.f; cq[j] = 0.f; }
        #pragma unroll
        for (int i = 0; i < 8; i++)
            #pragma unroll
            for (int j = 0; j < 4; j++) {
                float lo, hi; unpack2(acc[i][j], lo, hi);
                cs[2 * j] += lo;           cs[2 * j + 1] += hi;
                cq[2 * j] += lo * lo;      cq[2 * j + 1] += hi * hi;
            }
        __syncthreads();
        float* red = (float*)As2;   // 4096 floats: [0..2047]=sum, [2048..4095]=sq
        #pragma unroll
        for (int j = 0; j < 8; j++) {
            red[ty * 128 + tx * 8 + j] = cs[j];
            red[2048 + ty * 128 + tx * 8 + j] = cq[j];
        }
        __syncthreads();
        if (tid < 128) {
            float s = 0.f, q = 0.f;
            #pragma unroll
            for (int t = 0; t < 16; t++) {
                s += red[t * 128 + tid];
                q += red[2048 + t * 128 + tid];
            }
            atomicAdd(&g_bn[tid], s);
            atomicAdd(&g_bn[128 + tid], q);
        }
    }
}

__global__ void __launch_bounds__(256, 2)
gemm_emb_kernel(const float* __restrict__ feature, const float* __restrict__ emb_b) {
    gemm_core<false>(feature, g_embT, emb_b, g_h, HH);
}

__global__ void __launch_bounds__(256, 2)
gemm_layer_kernel(int l) {
    gemm_core<true>(g_s, &g_Bt[(size_t)l * KK3 * HH * HH], nullptr, g_agg, KK3 * HH);
}

// ---------------------------------------------------------------------------
// Edge weights for ALL layers in one pass (CSR-ordered)
// ---------------------------------------------------------------------------
__global__ void edge_weight_all_kernel(const float* __restrict__ pp_w,
                                       const float* __restrict__ pp_b,
                                       const float* __restrict__ mu,
                                       const float* __restrict__ inv_sigma) {
    int e = blockIdx.x * blockDim.x + threadIdx.x;
    if (e >= EE) return;
    float2 p = g_pseudo[e];
    #pragma unroll
    for (int l = 0; l < LL; l++) {
        float ps[2];
        #pragma unroll
        for (int d = 0; d < 2; d++) {
            float a = pp_w[(l * 2 + d) * 2 + 0] * p.x + pp_w[(l * 2 + d) * 2 + 1] * p.y
                    + pp_b[l * 2 + d];
            ps[d] = tanhf(a);
        }
        float wk[3];
        #pragma unroll
        for (int k = 0; k < 3; k++) {
            float acc = 0.f;
            #pragma unroll
            for (int d = 0; d < 2; d++) {
                float diff = ps[d] - mu[(l * 3 + k) * 2 + d];
                float is = inv_sigma[(l * 3 + k) * 2 + d];
                acc += diff * diff * is * is;
            }
            wk[k] = expf(-0.5f * acc);
        }
        g_w4[(size_t)l * EE + e] = make_float4(wk[0], wk[1], wk[2], 0.f);
    }
}

// ---------------------------------------------------------------------------
// Aggregation: one warp per destination node (packed f32x2)
//   g_s[c][k*H + i] = sum_{e -> c} w[e,k] * g_h[row_e][i]
// Also zeroes the BN accumulators (runs before gemm_layer each layer).
// ---------------------------------------------------------------------------
__global__ void aggregate_kernel(int l) {
    if (blockIdx.x == 0 && threadIdx.x < 256) g_bn[threadIdx.x] = 0.f;
    int gw = blockIdx.x * 8 + (threadIdx.x >> 5);
    int lane = threadIdx.x & 31;
    if (gw >= NN) return;
    int start = g_off[gw], end = g_off[gw + 1];
    const float4* __restrict__ wbase = &g_w4[(size_t)l * EE];

    u64 a00 = 0, a01 = 0, a10 = 0, a11 = 0, a20 = 0, a21 = 0;

    int e = start;
    int r_next = 0;
    float4 w_next = make_float4(0.f, 0.f, 0.f, 0.f);
    if (e < end) { r_next = g_csr_row[e]; w_next = wbase[e]; }
    for (; e < end; e++) {
        int r = r_next;
        float4 wv = w_next;
        if (e + 1 < end) { r_next = g_csr_row[e + 1]; w_next = wbase[e + 1]; }
        ulonglong2 hv = *(const ulonglong2*)&g_h[(size_t)r * HH + lane * 4];
        u64 w0 = pack2(wv.x, wv.x);
        u64 w1 = pack2(wv.y, wv.y);
        u64 w2 = pack2(wv.z, wv.z);
        ffma2(a00, w0, hv.x); ffma2(a01, w0, hv.y);
        ffma2(a10, w1, hv.x); ffma2(a11, w1, hv.y);
        ffma2(a20, w2, hv.x); ffma2(a21, w2, hv.y);
    }
    size_t base = (size_t)gw * (KK3 * HH) + lane * 4;
    *(ulonglong2*)&g_s[base]          = make_ulonglong2(a00, a01);
    *(ulonglong2*)&g_s[base + HH]     = make_ulonglong2(a10, a11);
    *(ulonglong2*)&g_s[base + 2 * HH] = make_ulonglong2(a20, a21);
}

// ---------------------------------------------------------------------------
// BN apply (ReLU + residual into g_h); stats already in g_bn from GEMM epilogue
// ---------------------------------------------------------------------------
__global__ void bn_apply_kernel(int l, const float* __restrict__ gamma,
                                const float* __restrict__ beta) {
    int idx = blockIdx.x * blockDim.x + threadIdx.x;     // over N*H/4
    if (idx >= NN * HH / 4) return;
    int ch = (idx * 4) & 127;
    const float inv_n = 1.0f / (float)NN;
    float4 a = *(const float4*)&g_agg[(size_t)idx * 4];
    float4 h = *(const float4*)&g_h[(size_t)idx * 4];
    #pragma unroll
    for (int c = 0; c < 4; c++) {
        float mean = g_bn[ch + c] * inv_n;
        float var = g_bn[128 + ch + c] * inv_n - mean * mean;
        float inv = rsqrtf(var + BN_EPS);
        float av = (c == 0) ? a.x : (c == 1) ? a.y : (c == 2) ? a.z : a.w;
        float hv = (c == 0) ? h.x : (c == 1) ? h.y : (c == 2) ? h.z : h.w;
        float bn = (av - mean) * inv * gamma[l * HH + ch + c] + beta[l * HH + ch + c];
        float nv = hv + fmaxf(bn, 0.f);
        if (c == 0) h.x = nv; else if (c == 1) h.y = nv;
        else if (c == 2) h.z = nv; else h.w = nv;
    }
    *(float4*)&g_h[(size_t)idx * 4] = h;
}

// ---------------------------------------------------------------------------
// Readout (mean per graph) + MLP head
// ---------------------------------------------------------------------------
__global__ void readout_kernel(const int* __restrict__ batch) {
    int g = blockIdx.x, tid = threadIdx.x;   // 128 threads
    int lo = 0, hi = NN;
    while (lo < hi) { int m = (lo + hi) >> 1; if (batch[m] < g) lo = m + 1; else hi = m; }
    int start = lo;
    lo = start; hi = NN;
    while (lo < hi) { int m = (lo + hi) >> 1; if (batch[m] <= g) lo = m + 1; else hi = m; }
    int end = lo;
    float acc = 0.f;
    for (int n = start; n < end; n++) acc += g_h[(size_t)n * HH + tid];
    float cnt = (float)(end - start);
    g_hg[g * HH + tid] = acc / fmaxf(cnt, 1.0f);
}

__global__ void mlp_kernel(const float* __restrict__ w0, const float* __restrict__ b0,
                           const float* __restrict__ w1, const float* __restrict__ b1,
                           const float* __restrict__ w2, const float* __restrict__ b2,
                           float* __restrict__ out) {
    __shared__ float sh[128], z0[64], z1[32];
    int g = blockIdx.x, tid = threadIdx.x;
    sh[tid] = g_hg[g * 128 + tid];
    __syncthreads();
    if (tid < 64) {
        float a = b0[tid];
        #pragma unroll 8
        for (int i = 0; i < 128; i++) a = fmaf(w0[tid * 128 + i], sh[i], a);
        z0[tid] = fmaxf(a, 0.f);
    }
    __syncthreads();
    if (tid < 32) {
        float a = b1[tid];
        #pragma unroll 8
        for (int i = 0; i < 64; i++) a = fmaf(w1[tid * 64 + i], z0[i], a);
        z1[tid] = fmaxf(a, 0.f);
    }
    __syncthreads();
    if (tid < 10) {
        float a = b2[tid];
        #pragma unroll
        for (int i = 0; i < 32; i++) a = fmaf(w2[tid * 32 + i], z1[i], a);
        out[g * NC + tid] = a;
    }
}

// ---------------------------------------------------------------------------
// Launch
// ---------------------------------------------------------------------------
extern "C" void kernel_launch(void* const* d_in, const int* in_sizes, int n_in,
                              void* d_out, int out_size) {
    const float* feature   = (const float*)d_in[0];
    const int*   edge_index= (const int*)  d_in[1];
    const int*   batch     = (const int*)  d_in[2];
    const float* emb_w     = (const float*)d_in[3];
    const float* emb_b     = (const float*)d_in[4];
    const float* fc_w      = (const float*)d_in[5];
    const float* mu        = (const float*)d_in[6];
    const float* inv_sigma = (const float*)d_in[7];
    const float* bn_gamma  = (const float*)d_in[8];
    const float* bn_beta   = (const float*)d_in[9];
    const float* pp_w      = (const float*)d_in[10];
    const float* pp_b      = (const float*)d_in[11];
    const float* mlp_w0    = (const float*)d_in[12];
    const float* mlp_b0    = (const float*)d_in[13];
    const float* mlp_w1    = (const float*)d_in[14];
    const float* mlp_b1    = (const float*)d_in[15];
    const float* mlp_w2    = (const float*)d_in[16];
    const float* mlp_b2    = (const float*)d_in[17];
    float* out = (float*)d_out;

    const int EB = (EE + 255) / 256;        // 3125
    const int GEMM_BLKS = (NN + 127) / 128; // 391

    // -------- precompute (per launch) --------
    zero_int3_kernel<<<(NN + 255) / 256, 256>>>();
    degrees_kernel<<<EB, 256>>>(edge_index);
    scan_kernel<<<1, 1024>>>();
    fill_csr_kernel<<<EB, 256>>>(edge_index);
    prep_weights_kernel<<<1024, 256>>>(emb_w, fc_w);
    edge_weight_all_kernel<<<EB, 256>>>(pp_w, pp_b, mu, inv_sigma);

    // embedding: h = feature @ emb_w.T + emb_b
    gemm_emb_kernel<<<GEMM_BLKS, 256>>>(feature, emb_b);

    // -------- layers --------
    for (int l = 0; l < LL; l++) {
        aggregate_kernel<<<(NN + 7) / 8, 256>>>(l);
        gemm_layer_kernel<<<GEMM_BLKS, 256>>>(l);
        bn_apply_kernel<<<(NN * HH / 4 + 255) / 256, 256>>>(l, bn_gamma, bn_beta);
    }

    // -------- readout + MLP --------
    readout_kernel<<<GG, 128>>>(batch);
    mlp_kernel<<<GG, 128>>>(mlp_w0, mlp_b0, mlp_w1, mlp_b1, mlp_w2, mlp_b2, out);
}